// round 14
// baseline (speedup 1.0000x reference)
#include <cuda_runtime.h>
#include <cuda_bf16.h>
#include <cstdint>
#include <math_constants.h>

#define M_ROWS   131072
#define N_VERTS  4000
#define N_PAD    4096
#define DIMS     16
#define KDIM     80            // [x1|x1|x2|x2|1,1,1] . [y1|y2|y1|y2|h1,h2,h3]
#define KC_N     5             // k16 chunks
#define CTA_M    256
#define GRID_M   (M_ROWS / CTA_M)     // 512
#define TILE_N   128
#define N_TILES  (N_PAD / TILE_N)     // 32
#define TAU      6e-4f

#define A_PITCH 176                   // 160B data + 16B pad
#define B_PITCH 192                   // 4 c-groups x 48B (40B data + 8B pad)
#define B_BYTES (TILE_N * B_PITCH)    // 24576
#define SMEM_A_OFF 0
#define SMEM_B_OFF (CTA_M * A_PITCH)               // 45056
#define SMEM_TOTAL (SMEM_B_OFF + B_BYTES)          // 69632

// Static device scratch (no allocs allowed)
__device__ __nv_bfloat16 g_A[(size_t)M_ROWS * KDIM];        // 21 MB
__device__ __nv_bfloat16 g_B[(size_t)N_PAD * (B_PITCH/2)];  // 768 KB (swizzled)
__device__ float         g_ysq[N_VERTS];

// ---------------------------------------------------------------------------
__device__ __forceinline__ void split2(float x, __nv_bfloat16& a, __nv_bfloat16& b) {
    a = __float2bfloat16_rn(x);
    b = __float2bfloat16_rn(x - __bfloat162float(a));
}
__device__ __forceinline__ void split3(float x, __nv_bfloat16& a, __nv_bfloat16& b,
                                       __nv_bfloat16& c) {
    a = __float2bfloat16_rn(x);
    float r = x - __bfloat162float(a);
    b = __float2bfloat16_rn(r);
    c = __float2bfloat16_rn(r - __bfloat162float(b));
}

// A row: [x1(16) | x1(16) | x2(16) | x2(16) | 1,1,1 | zeros..79]
__global__ void prep_a(const float* __restrict__ x) {
    int m = blockIdx.x * blockDim.x + threadIdx.x;
    if (m >= M_ROWS) return;
    __nv_bfloat16 row[KDIM];
#pragma unroll
    for (int k = 0; k < KDIM; ++k) row[k] = __float2bfloat16(0.f);
    const float4* xr = (const float4*)(x + (size_t)m * DIMS);
    float xs[DIMS];
#pragma unroll
    for (int i = 0; i < 4; ++i) {
        float4 v = xr[i];
        xs[4 * i] = v.x; xs[4 * i + 1] = v.y; xs[4 * i + 2] = v.z; xs[4 * i + 3] = v.w;
    }
#pragma unroll
    for (int d = 0; d < DIMS; ++d) {
        __nv_bfloat16 a, b;
        split2(xs[d], a, b);
        row[0 + d] = a; row[16 + d] = a; row[32 + d] = b; row[48 + d] = b;
    }
    row[64] = __float2bfloat16(1.f);
    row[65] = __float2bfloat16(1.f);
    row[66] = __float2bfloat16(1.f);
    uint4* dst = (uint4*)(g_A + (size_t)m * KDIM);
    const uint4* src = (const uint4*)row;
#pragma unroll
    for (int i = 0; i < 10; ++i) dst[i] = src[i];
}

// B row (logical k-order) then SWIZZLED store:
// word(c,kc,h) = bf16 pair at k = kc*16 + h*8 + c*2, stored at c*48 + kc*8 + h*4 bytes.
__global__ void prep_b(const float* __restrict__ y) {
    int n = blockIdx.x * blockDim.x + threadIdx.x;
    if (n >= N_PAD) return;
    __nv_bfloat16 row[KDIM];
#pragma unroll
    for (int k = 0; k < KDIM; ++k) row[k] = __float2bfloat16(0.f);
    if (n < N_VERTS) {
        const float* yr = y + (size_t)n * DIMS;
        float h = 0.f;
#pragma unroll
        for (int d = 0; d < DIMS; ++d) {
            float v = yr[d];
            h = fmaf(v, v, h);
            __nv_bfloat16 a, b;
            split2(v, a, b);
            row[0 + d] = a; row[16 + d] = b; row[32 + d] = a; row[48 + d] = b;
        }
        g_ysq[n] = h;
        __nv_bfloat16 h1, h2, h3;
        split3(-0.5f * h, h1, h2, h3);
        row[64] = h1; row[65] = h2; row[66] = h3;
    } else {
        row[64] = __float2bfloat16(-1e30f);  // never wins (A k64 = 1)
    }
    __nv_bfloat16 sw[B_PITCH / 2];
#pragma unroll
    for (int i = 0; i < B_PITCH / 2; ++i) sw[i] = __float2bfloat16(0.f);
#pragma unroll
    for (int c = 0; c < 4; ++c)
#pragma unroll
        for (int kc = 0; kc < KC_N; ++kc)
#pragma unroll
            for (int hh = 0; hh < 2; ++hh) {
                int k = kc * 16 + hh * 8 + c * 2;
                sw[c * 24 + kc * 4 + hh * 2 + 0] = row[k];
                sw[c * 24 + kc * 4 + hh * 2 + 1] = row[k + 1];
            }
    uint4* dst = (uint4*)(g_B + (size_t)n * (B_PITCH / 2));
    const uint4* src = (const uint4*)sw;
#pragma unroll
    for (int i = 0; i < B_PITCH / 16; ++i) dst[i] = src[i];
}

// ---------------------------------------------------------------------------
__device__ __forceinline__ void mma16816(float* d, const uint32_t* a,
                                         const uint32_t* b) {
    asm volatile(
        "mma.sync.aligned.m16n8k16.row.col.f32.bf16.bf16.f32 "
        "{%0,%1,%2,%3}, {%4,%5,%6,%7}, {%8,%9}, {%0,%1,%2,%3};"
        : "+f"(d[0]), "+f"(d[1]), "+f"(d[2]), "+f"(d[3])
        : "r"(a[0]), "r"(a[1]), "r"(a[2]), "r"(a[3]), "r"(b[0]), "r"(b[1]));
}

__device__ __forceinline__ void load_bfrag(uint32_t bf[KC_N][2], const char* base) {
    uint4 w0 = *(const uint4*)(base);
    uint4 w1 = *(const uint4*)(base + 16);
    uint2 w2 = *(const uint2*)(base + 32);
    bf[0][0] = w0.x; bf[0][1] = w0.y; bf[1][0] = w0.z; bf[1][1] = w0.w;
    bf[2][0] = w1.x; bf[2][1] = w1.y; bf[3][0] = w1.z; bf[3][1] = w1.w;
    bf[4][0] = w2.x; bf[4][1] = w2.y;
}

// One nb2 sub-iteration: 2 B fragments, 20 HMMA, per-row max-of-4 only.
__device__ __forceinline__ void compute_m4(const char* sB, int nb2, int g, int c,
                                           const uint32_t af[2][KC_N][4],
                                           float m4[4]) {
    uint32_t bfA[KC_N][2], bfB[KC_N][2];
    load_bfrag(bfA, sB + (nb2 * 16 + g) * B_PITCH + c * 48);
    load_bfrag(bfB, sB + (nb2 * 16 + 8 + g) * B_PITCH + c * 48);

    float a0A[4] = {0.f, 0.f, 0.f, 0.f};
    float a1A[4] = {0.f, 0.f, 0.f, 0.f};
    float a0B[4] = {0.f, 0.f, 0.f, 0.f};
    float a1B[4] = {0.f, 0.f, 0.f, 0.f};
#pragma unroll
    for (int kc = 0; kc < KC_N; ++kc) {
        mma16816(a0A, af[0][kc], bfA[kc]);
        mma16816(a1A, af[1][kc], bfA[kc]);
        mma16816(a0B, af[0][kc], bfB[kc]);
        mma16816(a1B, af[1][kc], bfB[kc]);
    }
    m4[0] = fmaxf(fmaxf(a0A[0], a0A[1]), fmaxf(a0B[0], a0B[1]));
    m4[1] = fmaxf(fmaxf(a0A[2], a0A[3]), fmaxf(a0B[2], a0B[3]));
    m4[2] = fmaxf(fmaxf(a1A[0], a1A[1]), fmaxf(a1B[0], a1B[1]));
    m4[3] = fmaxf(fmaxf(a1A[2], a1A[3]), fmaxf(a1B[2], a1B[3]));
}

// Exact R1-proven fp32 scoring (init -0.5*ysq, ascending fmaf chain)
__device__ __forceinline__ float score_one(const float* xs, const float4* yv,
                                           float ysq) {
    float4 y0 = yv[0], y1 = yv[1], y2 = yv[2], y3 = yv[3];
    float acc = -0.5f * ysq;
    acc = fmaf(xs[0], y0.x, acc);  acc = fmaf(xs[1], y0.y, acc);
    acc = fmaf(xs[2], y0.z, acc);  acc = fmaf(xs[3], y0.w, acc);
    acc = fmaf(xs[4], y1.x, acc);  acc = fmaf(xs[5], y1.y, acc);
    acc = fmaf(xs[6], y1.z, acc);  acc = fmaf(xs[7], y1.w, acc);
    acc = fmaf(xs[8], y2.x, acc);  acc = fmaf(xs[9], y2.y, acc);
    acc = fmaf(xs[10], y2.z, acc); acc = fmaf(xs[11], y2.w, acc);
    acc = fmaf(xs[12], y3.x, acc); acc = fmaf(xs[13], y3.y, acc);
    acc = fmaf(xs[14], y3.z, acc); acc = fmaf(xs[15], y3.w, acc);
    return acc;
}

// ---------------------------------------------------------------------------
// Main kernel: MMA loop; bookkeeping merged over PAIRS of nb2 iterations
// (8-column groups). Endgame resolves the winning group exactly in fp32;
// cross-group gap < TAU rows go to the fused per-CTA rescue tail.
// ---------------------------------------------------------------------------
__global__ void __launch_bounds__(256, 2)
nn_mma_kernel(const float* __restrict__ x,
              const float* __restrict__ verts,
              const float* __restrict__ colors,
              float* __restrict__ out) {
    extern __shared__ char smem[];
    char* sA = smem + SMEM_A_OFF;
    char* sB = smem + SMEM_B_OFF;
    __shared__ int s_cnt;
    __shared__ int s_list[CTA_M];

    const int tid = threadIdx.x;
    const int w = tid >> 5;
    const int lane = tid & 31;
    const int g = lane >> 2;
    const int c = lane & 3;
    const int m0 = blockIdx.x * CTA_M;

    if (tid == 0) s_cnt = 0;

    // Load A stripe (256 x 80 bf16) into padded smem rows
    {
        const uint4* src = (const uint4*)(g_A + (size_t)m0 * KDIM);
        for (int i = tid; i < CTA_M * 10; i += 256) {
            int r = i / 10, j = i - r * 10;
            *(uint4*)(sA + r * A_PITCH + j * 16) = src[i];
        }
    }
    __syncthreads();

    // A fragments: 2 stripes x 5 k-chunks x 4 regs (live all kernel)
    uint32_t af[2][KC_N][4];
#pragma unroll
    for (int s = 0; s < 2; ++s) {
        int r0 = w * 32 + s * 16 + g;
#pragma unroll
        for (int kc = 0; kc < KC_N; ++kc) {
            const char* base = sA + r0 * A_PITCH + kc * 32 + c * 4;
            af[s][kc][0] = *(const uint32_t*)(base);
            af[s][kc][1] = *(const uint32_t*)(base + 8 * A_PITCH);
            af[s][kc][2] = *(const uint32_t*)(base + 16);
            af[s][kc][3] = *(const uint32_t*)(base + 8 * A_PITCH + 16);
        }
    }

    float b1[4] = {-CUDART_INF_F, -CUDART_INF_F, -CUDART_INF_F, -CUDART_INF_F};
    float b2[4] = {-CUDART_INF_F, -CUDART_INF_F, -CUDART_INF_F, -CUDART_INF_F};
    int rec[4] = {0, 0, 0, 0};

    for (int t = 0; t < N_TILES; ++t) {
        __syncthreads();
        {
            const uint4* src = (const uint4*)(g_B + (size_t)t * TILE_N * (B_PITCH / 2));
            uint4* dst = (uint4*)sB;
            for (int i = tid; i < TILE_N * (B_PITCH / 16); i += 256) dst[i] = src[i];
        }
        __syncthreads();

#pragma unroll 1
        for (int j = 0; j < 4; ++j) {
            float mA[4], mB[4];
            compute_m4(sB, 2 * j,     g, c, af, mA);
            compute_m4(sB, 2 * j + 1, g, c, af, mB);
            // 8-column group id: (t, j, c) packed
            const int gid = (((t << 2) | j) << 2) | c;
#pragma unroll
            for (int r = 0; r < 4; ++r) {
                float m = fmaxf(mA[r], mB[r]);
                b2[r] = fmaxf(b2[r], fminf(b1[r], m));
                if (m > b1[r]) rec[r] = gid;
                b1[r] = fmaxf(b1[r], m);
            }
        }
    }

    // Quad reduce (lanes 4g..4g+3 cover same rows, disjoint column groups).
    // Cross-lane approx ties end up flagged (gap 0 < TAU).
#pragma unroll
    for (int off = 1; off <= 2; off <<= 1) {
#pragma unroll
        for (int r = 0; r < 4; ++r) {
            float ob1 = __shfl_xor_sync(0xFFFFFFFFu, b1[r], off);
            float ob2 = __shfl_xor_sync(0xFFFFFFFFu, b2[r], off);
            int orec = __shfl_xor_sync(0xFFFFFFFFu, rec[r], off);
            b2[r] = fmaxf(fmaxf(b2[r], ob2), fminf(b1[r], ob1));
            if (ob1 > b1[r]) rec[r] = orec;
            b1[r] = fmaxf(b1[r], ob1);
        }
    }

    if (c == 0) {
        const int rows[4] = {m0 + w * 32 + g,      m0 + w * 32 + g + 8,
                             m0 + w * 32 + g + 16, m0 + w * 32 + g + 24};
#pragma unroll
        for (int r = 0; r < 4; ++r) {
            if (b1[r] - b2[r] < TAU) {
                int f = atomicAdd(&s_cnt, 1);
                s_list[f] = rows[r];
            } else {
                // Winner provably in recorded 8-col group: resolve exactly.
                float xs[DIMS];
                const float4* xr = (const float4*)(x + (size_t)rows[r] * DIMS);
#pragma unroll
                for (int i = 0; i < 4; ++i) {
                    float4 v = xr[i];
                    xs[4 * i] = v.x; xs[4 * i + 1] = v.y;
                    xs[4 * i + 2] = v.z; xs[4 * i + 3] = v.w;
                }
                const int rv = rec[r];
                const int cw = rv & 3;
                const int tj = rv >> 2;
                const int base = (tj >> 2) * TILE_N + (tj & 3) * 32 + cw * 2;
                float bestv = -CUDART_INF_F;
                int bi = 0;
#pragma unroll
                for (int jj = 0; jj < 8; ++jj) {
                    const int v = base + (jj >> 1) * 8 + (jj & 1);
                    if (v < N_VERTS) {
                        float s = score_one(xs, (const float4*)(verts + (size_t)v * DIMS),
                                            g_ysq[v]);
                        if (s > bestv) { bestv = s; bi = v; }
                    }
                }
                const float* cc = colors + (size_t)3 * bi;
                float* o = out + (size_t)3 * rows[r];
                o[0] = cc[0]; o[1] = cc[1]; o[2] = cc[2];
            }
        }
    }
    __syncthreads();

    // ---- Fused rescue tail: warp-per-flagged-row exact fp32 argmax ----
    const int cntL = s_cnt;
    for (int f = w; f < cntL; f += 8) {
        const int row = s_list[f];
        float xs[DIMS];
        const float4* xr = (const float4*)(x + (size_t)row * DIMS);
#pragma unroll
        for (int i = 0; i < 4; ++i) {
            float4 v = xr[i];
            xs[4 * i] = v.x; xs[4 * i + 1] = v.y;
            xs[4 * i + 2] = v.z; xs[4 * i + 3] = v.w;
        }

        float best = -CUDART_INF_F;
        int bi = N_VERTS;
        for (int base = 0; base < 3968; base += 128) {
            const int v0 = base + lane * 4;
            const float4* yv = (const float4*)(verts + (size_t)v0 * DIMS);
            float s0 = score_one(xs, yv + 0,  g_ysq[v0 + 0]);
            float s1 = score_one(xs, yv + 4,  g_ysq[v0 + 1]);
            float s2 = score_one(xs, yv + 8,  g_ysq[v0 + 2]);
            float s3 = score_one(xs, yv + 12, g_ysq[v0 + 3]);
            if (s0 > best) { best = s0; bi = v0; }
            if (s1 > best) { best = s1; bi = v0 + 1; }
            if (s2 > best) { best = s2; bi = v0 + 2; }
            if (s3 > best) { best = s3; bi = v0 + 3; }
        }
        {   // tail verts 3968..3999
            const int v0 = 3968 + lane;
            const float4* yv = (const float4*)(verts + (size_t)v0 * DIMS);
            float s0 = score_one(xs, yv, g_ysq[v0]);
            if (s0 > best) { best = s0; bi = v0; }
        }
#pragma unroll
        for (int off = 16; off > 0; off >>= 1) {
            float os = __shfl_down_sync(0xFFFFFFFF, best, off);
            int oi = __shfl_down_sync(0xFFFFFFFF, bi, off);
            if (os > best || (os == best && oi < bi)) { best = os; bi = oi; }
        }
        if (lane == 0) {
            const float* cc = colors + (size_t)3 * bi;
            float* o = out + (size_t)3 * row;
            o[0] = cc[0]; o[1] = cc[1]; o[2] = cc[2];
        }
    }
}

extern "C" void kernel_launch(void* const* d_in, const int* in_sizes, int n_in,
                              void* d_out, int out_size) {
    const float* cse    = (const float*)d_in[0];  // (M,16) f32
    const float* colors = (const float*)d_in[1];  // (N,3)  f32
    const float* vemb   = (const float*)d_in[2];  // (N,16) f32
    float* out = (float*)d_out;                   // (M,3)  f32

    cudaFuncSetAttribute(nn_mma_kernel,
                         cudaFuncAttributeMaxDynamicSharedMemorySize, SMEM_TOTAL);

    prep_b<<<(N_PAD + 255) / 256, 256>>>(vemb);
    prep_a<<<(M_ROWS + 255) / 256, 256>>>(cse);
    nn_mma_kernel<<<GRID_M, 256, SMEM_TOTAL>>>(cse, vemb, colors, out);
}

// round 15
// speedup vs baseline: 1.5555x; 1.5555x over previous
#include <cuda_runtime.h>
#include <cuda_bf16.h>
#include <cstdint>
#include <math_constants.h>

#define M_ROWS   131072
#define N_VERTS  4000
#define N_PAD    4096
#define DIMS     16
#define KDIM     80            // [x1|x1|x2|x2|1,1,1] . [y1|y2|y1|y2|h1,h2,h3]
#define KC_N     5             // k16 chunks
#define CTA_M    256
#define GRID_M   (M_ROWS / CTA_M)     // 512
#define TILE_N   128
#define N_TILES  (N_PAD / TILE_N)     // 32
#define TAU      6e-4f

#define A_PITCH 176                   // 160B data + 16B pad
#define B_PITCH 192                   // 4 c-groups x 48B (40B data + 8B pad)
#define B_BYTES (TILE_N * B_PITCH)    // 24576
#define SMEM_A_OFF 0
#define SMEM_B_OFF (CTA_M * A_PITCH)               // 45056
#define SMEM_TOTAL (SMEM_B_OFF + B_BYTES)          // 69632

// Static device scratch (no allocs allowed)
__device__ __nv_bfloat16 g_B[(size_t)N_PAD * (B_PITCH/2)];  // 768 KB (swizzled)
__device__ float         g_ysq[N_VERTS];

// ---------------------------------------------------------------------------
__device__ __forceinline__ void split2(float x, __nv_bfloat16& a, __nv_bfloat16& b) {
    a = __float2bfloat16_rn(x);
    b = __float2bfloat16_rn(x - __bfloat162float(a));
}
__device__ __forceinline__ void split3(float x, __nv_bfloat16& a, __nv_bfloat16& b,
                                       __nv_bfloat16& c) {
    a = __float2bfloat16_rn(x);
    float r = x - __bfloat162float(a);
    b = __float2bfloat16_rn(r);
    c = __float2bfloat16_rn(r - __bfloat162float(b));
}

// B row (logical k-order) then SWIZZLED store:
// word(c,kc,h) = bf16 pair at k = kc*16 + h*8 + c*2, stored at c*48 + kc*8 + h*4 bytes.
__global__ void prep_b(const float* __restrict__ y) {
    int n = blockIdx.x * blockDim.x + threadIdx.x;
    if (n >= N_PAD) return;
    __nv_bfloat16 row[KDIM];
#pragma unroll
    for (int k = 0; k < KDIM; ++k) row[k] = __float2bfloat16(0.f);
    if (n < N_VERTS) {
        const float* yr = y + (size_t)n * DIMS;
        float h = 0.f;
#pragma unroll
        for (int d = 0; d < DIMS; ++d) {
            float v = yr[d];
            h = fmaf(v, v, h);
            __nv_bfloat16 a, b;
            split2(v, a, b);
            row[0 + d] = a; row[16 + d] = b; row[32 + d] = a; row[48 + d] = b;
        }
        g_ysq[n] = h;
        __nv_bfloat16 h1, h2, h3;
        split3(-0.5f * h, h1, h2, h3);
        row[64] = h1; row[65] = h2; row[66] = h3;
    } else {
        row[64] = __float2bfloat16(-1e30f);  // never wins (A k64 = 1)
    }
    __nv_bfloat16 sw[B_PITCH / 2];
#pragma unroll
    for (int i = 0; i < B_PITCH / 2; ++i) sw[i] = __float2bfloat16(0.f);
#pragma unroll
    for (int c = 0; c < 4; ++c)
#pragma unroll
        for (int kc = 0; kc < KC_N; ++kc)
#pragma unroll
            for (int hh = 0; hh < 2; ++hh) {
                int k = kc * 16 + hh * 8 + c * 2;
                sw[c * 24 + kc * 4 + hh * 2 + 0] = row[k];
                sw[c * 24 + kc * 4 + hh * 2 + 1] = row[k + 1];
            }
    uint4* dst = (uint4*)(g_B + (size_t)n * (B_PITCH / 2));
    const uint4* src = (const uint4*)sw;
#pragma unroll
    for (int i = 0; i < B_PITCH / 16; ++i) dst[i] = src[i];
}

// ---------------------------------------------------------------------------
__device__ __forceinline__ void mma16816(float* d, const uint32_t* a,
                                         const uint32_t* b) {
    asm volatile(
        "mma.sync.aligned.m16n8k16.row.col.f32.bf16.bf16.f32 "
        "{%0,%1,%2,%3}, {%4,%5,%6,%7}, {%8,%9}, {%0,%1,%2,%3};"
        : "+f"(d[0]), "+f"(d[1]), "+f"(d[2]), "+f"(d[3])
        : "r"(a[0]), "r"(a[1]), "r"(a[2]), "r"(a[3]), "r"(b[0]), "r"(b[1]));
}

// Group update: m = max of 4 candidates; b2' tracks 2nd-best GROUP max;
// rec records the (tile,nb2,c) group that last strictly improved b1.
__device__ __forceinline__ void upd4(float v0, float v1, float v2, float v3,
                                     int gid, float& b1, float& b2, int& rec) {
    float m = fmaxf(fmaxf(v0, v1), fmaxf(v2, v3));
    b2 = fmaxf(b2, fminf(b1, m));
    if (m > b1) rec = gid;
    b1 = fmaxf(b1, m);
}

__device__ __forceinline__ void load_bfrag(uint32_t bf[KC_N][2], const char* base) {
    uint4 w0 = *(const uint4*)(base);
    uint4 w1 = *(const uint4*)(base + 16);
    uint2 w2 = *(const uint2*)(base + 32);
    bf[0][0] = w0.x; bf[0][1] = w0.y; bf[1][0] = w0.z; bf[1][1] = w0.w;
    bf[2][0] = w1.x; bf[2][1] = w1.y; bf[3][0] = w1.z; bf[3][1] = w1.w;
    bf[4][0] = w2.x; bf[4][1] = w2.y;
}

// Exact R1-proven fp32 scoring (init -0.5*ysq, ascending fmaf chain)
__device__ __forceinline__ float score_one(const float* xs, const float4* yv,
                                           float ysq) {
    float4 y0 = yv[0], y1 = yv[1], y2 = yv[2], y3 = yv[3];
    float acc = -0.5f * ysq;
    acc = fmaf(xs[0], y0.x, acc);  acc = fmaf(xs[1], y0.y, acc);
    acc = fmaf(xs[2], y0.z, acc);  acc = fmaf(xs[3], y0.w, acc);
    acc = fmaf(xs[4], y1.x, acc);  acc = fmaf(xs[5], y1.y, acc);
    acc = fmaf(xs[6], y1.z, acc);  acc = fmaf(xs[7], y1.w, acc);
    acc = fmaf(xs[8], y2.x, acc);  acc = fmaf(xs[9], y2.y, acc);
    acc = fmaf(xs[10], y2.z, acc); acc = fmaf(xs[11], y2.w, acc);
    acc = fmaf(xs[12], y3.x, acc); acc = fmaf(xs[13], y3.y, acc);
    acc = fmaf(xs[14], y3.z, acc); acc = fmaf(xs[15], y3.w, acc);
    return acc;
}

// ---------------------------------------------------------------------------
// Main kernel (R13 loop, byte-identical) with IN-KERNEL A split: each thread
// reads its raw X row (fp32) and writes the split-bf16 A row directly to the
// padded smem tile — no prep_a pass, no g_A round-trip.
// ---------------------------------------------------------------------------
__global__ void __launch_bounds__(256, 2)
nn_mma_kernel(const float* __restrict__ x,
              const float* __restrict__ verts,
              const float* __restrict__ colors,
              float* __restrict__ out) {
    extern __shared__ char smem[];
    char* sA = smem + SMEM_A_OFF;
    char* sB = smem + SMEM_B_OFF;
    __shared__ int s_cnt;
    __shared__ int s_list[CTA_M];

    const int tid = threadIdx.x;
    const int w = tid >> 5;
    const int lane = tid & 31;
    const int g = lane >> 2;
    const int c = lane & 3;
    const int m0 = blockIdx.x * CTA_M;

    if (tid == 0) s_cnt = 0;

    // Build A stripe in smem: thread tid owns row tid (global row m0+tid).
    // Layout identical to R13's prep_a: [x1(16)|x1(16)|x2(16)|x2(16)|1,1,1|0..]
    {
        const float4* xr = (const float4*)(x + (size_t)(m0 + tid) * DIMS);
        float xs[DIMS];
#pragma unroll
        for (int i = 0; i < 4; ++i) {
            float4 v = xr[i];
            xs[4 * i] = v.x; xs[4 * i + 1] = v.y;
            xs[4 * i + 2] = v.z; xs[4 * i + 3] = v.w;
        }
        __nv_bfloat16 row[KDIM];
#pragma unroll
        for (int k = 0; k < KDIM; ++k) row[k] = __float2bfloat16(0.f);
#pragma unroll
        for (int d = 0; d < DIMS; ++d) {
            __nv_bfloat16 a, b;
            split2(xs[d], a, b);
            row[0 + d] = a; row[16 + d] = a; row[32 + d] = b; row[48 + d] = b;
        }
        row[64] = __float2bfloat16(1.f);
        row[65] = __float2bfloat16(1.f);
        row[66] = __float2bfloat16(1.f);
        const uint4* src = (const uint4*)row;
        uint4* dst = (uint4*)(sA + tid * A_PITCH);
#pragma unroll
        for (int i = 0; i < 10; ++i) dst[i] = src[i];
    }
    __syncthreads();

    // A fragments: 2 stripes x 5 k-chunks x 4 regs (live all kernel)
    uint32_t af[2][KC_N][4];
#pragma unroll
    for (int s = 0; s < 2; ++s) {
        int r0 = w * 32 + s * 16 + g;
#pragma unroll
        for (int kc = 0; kc < KC_N; ++kc) {
            const char* base = sA + r0 * A_PITCH + kc * 32 + c * 4;
            af[s][kc][0] = *(const uint32_t*)(base);
            af[s][kc][1] = *(const uint32_t*)(base + 8 * A_PITCH);
            af[s][kc][2] = *(const uint32_t*)(base + 16);
            af[s][kc][3] = *(const uint32_t*)(base + 8 * A_PITCH + 16);
        }
    }

    float b1[4] = {-CUDART_INF_F, -CUDART_INF_F, -CUDART_INF_F, -CUDART_INF_F};
    float b2[4] = {-CUDART_INF_F, -CUDART_INF_F, -CUDART_INF_F, -CUDART_INF_F};
    int rec[4] = {0, 0, 0, 0};

    for (int t = 0; t < N_TILES; ++t) {
        __syncthreads();
        {
            const uint4* src = (const uint4*)(g_B + (size_t)t * TILE_N * (B_PITCH / 2));
            uint4* dst = (uint4*)sB;
            for (int i = tid; i < TILE_N * (B_PITCH / 16); i += 256) dst[i] = src[i];
        }
        __syncthreads();

#pragma unroll 1
        for (int nb2 = 0; nb2 < 8; ++nb2) {
            uint32_t bfA[KC_N][2], bfB[KC_N][2];
            load_bfrag(bfA, sB + (nb2 * 16 + g) * B_PITCH + c * 48);
            load_bfrag(bfB, sB + (nb2 * 16 + 8 + g) * B_PITCH + c * 48);

            float a0A[4] = {0.f, 0.f, 0.f, 0.f};
            float a1A[4] = {0.f, 0.f, 0.f, 0.f};
            float a0B[4] = {0.f, 0.f, 0.f, 0.f};
            float a1B[4] = {0.f, 0.f, 0.f, 0.f};
#pragma unroll
            for (int kc = 0; kc < KC_N; ++kc) {
                mma16816(a0A, af[0][kc], bfA[kc]);
                mma16816(a1A, af[1][kc], bfA[kc]);
                mma16816(a0B, af[0][kc], bfB[kc]);
                mma16816(a1B, af[1][kc], bfB[kc]);
            }
            // group id: (t, nb2, c) packed
            const int gid = (((t << 3) | nb2) << 2) | c;
            upd4(a0A[0], a0A[1], a0B[0], a0B[1], gid, b1[0], b2[0], rec[0]);
            upd4(a0A[2], a0A[3], a0B[2], a0B[3], gid, b1[1], b2[1], rec[1]);
            upd4(a1A[0], a1A[1], a1B[0], a1B[1], gid, b1[2], b2[2], rec[2]);
            upd4(a1A[2], a1A[3], a1B[2], a1B[3], gid, b1[3], b2[3], rec[3]);
        }
    }

    // Quad reduce (lanes 4g..4g+3 cover same rows, disjoint column groups).
    // Cross-lane approx ties end up flagged (gap 0 < TAU).
#pragma unroll
    for (int off = 1; off <= 2; off <<= 1) {
#pragma unroll
        for (int r = 0; r < 4; ++r) {
            float ob1 = __shfl_xor_sync(0xFFFFFFFFu, b1[r], off);
            float ob2 = __shfl_xor_sync(0xFFFFFFFFu, b2[r], off);
            int orec = __shfl_xor_sync(0xFFFFFFFFu, rec[r], off);
            b2[r] = fmaxf(fmaxf(b2[r], ob2), fminf(b1[r], ob1));
            if (ob1 > b1[r]) rec[r] = orec;
            b1[r] = fmaxf(b1[r], ob1);
        }
    }

    if (c == 0) {
        const int rows[4] = {m0 + w * 32 + g,      m0 + w * 32 + g + 8,
                             m0 + w * 32 + g + 16, m0 + w * 32 + g + 24};
#pragma unroll
        for (int r = 0; r < 4; ++r) {
            if (b1[r] - b2[r] < TAU) {
                int f = atomicAdd(&s_cnt, 1);
                s_list[f] = rows[r];
            } else {
                // Winner provably in recorded group: resolve exactly in fp32.
                float xs[DIMS];
                const float4* xr = (const float4*)(x + (size_t)rows[r] * DIMS);
#pragma unroll
                for (int i = 0; i < 4; ++i) {
                    float4 v = xr[i];
                    xs[4 * i] = v.x; xs[4 * i + 1] = v.y;
                    xs[4 * i + 2] = v.z; xs[4 * i + 3] = v.w;
                }
                const int rv = rec[r];
                const int cw = rv & 3;
                const int tn = rv >> 2;
                const int base = (tn >> 3) * TILE_N + (tn & 7) * 16 + cw * 2;
                const int cols[4] = {base, base + 1, base + 8, base + 9};
                float bestv = -CUDART_INF_F;
                int bi = 0;
#pragma unroll
                for (int j = 0; j < 4; ++j) {
                    const int v = cols[j];
                    if (v < N_VERTS) {
                        float s = score_one(xs, (const float4*)(verts + (size_t)v * DIMS),
                                            g_ysq[v]);
                        if (s > bestv) { bestv = s; bi = v; }
                    }
                }
                const float* cc = colors + (size_t)3 * bi;
                float* o = out + (size_t)3 * rows[r];
                o[0] = cc[0]; o[1] = cc[1]; o[2] = cc[2];
            }
        }
    }
    __syncthreads();

    // ---- Fused rescue tail: warp-per-flagged-row exact fp32 argmax ----
    const int cntL = s_cnt;
    for (int f = w; f < cntL; f += 8) {
        const int row = s_list[f];
        float xs[DIMS];
        const float4* xr = (const float4*)(x + (size_t)row * DIMS);
#pragma unroll
        for (int i = 0; i < 4; ++i) {
            float4 v = xr[i];
            xs[4 * i] = v.x; xs[4 * i + 1] = v.y;
            xs[4 * i + 2] = v.z; xs[4 * i + 3] = v.w;
        }

        float best = -CUDART_INF_F;
        int bi = N_VERTS;
        for (int base = 0; base < 3968; base += 128) {
            const int v0 = base + lane * 4;
            const float4* yv = (const float4*)(verts + (size_t)v0 * DIMS);
            float s0 = score_one(xs, yv + 0,  g_ysq[v0 + 0]);
            float s1 = score_one(xs, yv + 4,  g_ysq[v0 + 1]);
            float s2 = score_one(xs, yv + 8,  g_ysq[v0 + 2]);
            float s3 = score_one(xs, yv + 12, g_ysq[v0 + 3]);
            if (s0 > best) { best = s0; bi = v0; }
            if (s1 > best) { best = s1; bi = v0 + 1; }
            if (s2 > best) { best = s2; bi = v0 + 2; }
            if (s3 > best) { best = s3; bi = v0 + 3; }
        }
        {   // tail verts 3968..3999
            const int v0 = 3968 + lane;
            const float4* yv = (const float4*)(verts + (size_t)v0 * DIMS);
            float s0 = score_one(xs, yv, g_ysq[v0]);
            if (s0 > best) { best = s0; bi = v0; }
        }
#pragma unroll
        for (int off = 16; off > 0; off >>= 1) {
            float os = __shfl_down_sync(0xFFFFFFFF, best, off);
            int oi = __shfl_down_sync(0xFFFFFFFF, bi, off);
            if (os > best || (os == best && oi < bi)) { best = os; bi = oi; }
        }
        if (lane == 0) {
            const float* cc = colors + (size_t)3 * bi;
            float* o = out + (size_t)3 * row;
            o[0] = cc[0]; o[1] = cc[1]; o[2] = cc[2];
        }
    }
}

extern "C" void kernel_launch(void* const* d_in, const int* in_sizes, int n_in,
                              void* d_out, int out_size) {
    const float* cse    = (const float*)d_in[0];  // (M,16) f32
    const float* colors = (const float*)d_in[1];  // (N,3)  f32
    const float* vemb   = (const float*)d_in[2];  // (N,16) f32
    float* out = (float*)d_out;                   // (M,3)  f32

    cudaFuncSetAttribute(nn_mma_kernel,
                         cudaFuncAttributeMaxDynamicSharedMemorySize, SMEM_TOTAL);

    prep_b<<<(N_PAD + 255) / 256, 256>>>(vemb);
    nn_mma_kernel<<<GRID_M, 256, SMEM_TOTAL>>>(cse, vemb, colors, out);
}

// round 16
// speedup vs baseline: 1.6671x; 1.0717x over previous
#include <cuda_runtime.h>
#include <cuda_bf16.h>
#include <cstdint>
#include <math_constants.h>

#define M_ROWS   131072
#define N_VERTS  4000
#define N_PAD    4096
#define DIMS     16
#define KDIM     80            // [x1|x1|x2|x2|1,1,1] . [y1|y2|y1|y2|h1,h2,h3]
#define KC_N     5             // k16 chunks
#define CTA_M    256
#define GRID_M   (M_ROWS / CTA_M)     // 512
#define TILE_N   256
#define N_TILES  (N_PAD / TILE_N)     // 16
#define NB2_N    (TILE_N / 16)        // 16
#define TAU      6e-4f

#define A_PITCH 176                   // 160B data + 16B pad
#define B_PITCH 192                   // 4 c-groups x 48B (40B data + 8B pad)
#define B_BYTES (TILE_N * B_PITCH)    // 49152
#define SMEM_A_OFF 0
#define SMEM_B_OFF (CTA_M * A_PITCH)               // 45056
#define SMEM_TOTAL (SMEM_B_OFF + B_BYTES)          // 94208

// Static device scratch (no allocs allowed)
__device__ __nv_bfloat16 g_B[(size_t)N_PAD * (B_PITCH/2)];  // 768 KB (swizzled)
__device__ float         g_ysq[N_VERTS];

// ---------------------------------------------------------------------------
__device__ __forceinline__ void split2(float x, __nv_bfloat16& a, __nv_bfloat16& b) {
    a = __float2bfloat16_rn(x);
    b = __float2bfloat16_rn(x - __bfloat162float(a));
}
__device__ __forceinline__ void split3(float x, __nv_bfloat16& a, __nv_bfloat16& b,
                                       __nv_bfloat16& c) {
    a = __float2bfloat16_rn(x);
    float r = x - __bfloat162float(a);
    b = __float2bfloat16_rn(r);
    c = __float2bfloat16_rn(r - __bfloat162float(b));
}

// B row (logical k-order) then SWIZZLED store:
// word(c,kc,h) = bf16 pair at k = kc*16 + h*8 + c*2, stored at c*48 + kc*8 + h*4 bytes.
__global__ void prep_b(const float* __restrict__ y) {
    int n = blockIdx.x * blockDim.x + threadIdx.x;
    if (n >= N_PAD) return;
    __nv_bfloat16 row[KDIM];
#pragma unroll
    for (int k = 0; k < KDIM; ++k) row[k] = __float2bfloat16(0.f);
    if (n < N_VERTS) {
        const float* yr = y + (size_t)n * DIMS;
        float h = 0.f;
#pragma unroll
        for (int d = 0; d < DIMS; ++d) {
            float v = yr[d];
            h = fmaf(v, v, h);
            __nv_bfloat16 a, b;
            split2(v, a, b);
            row[0 + d] = a; row[16 + d] = b; row[32 + d] = a; row[48 + d] = b;
        }
        g_ysq[n] = h;
        __nv_bfloat16 h1, h2, h3;
        split3(-0.5f * h, h1, h2, h3);
        row[64] = h1; row[65] = h2; row[66] = h3;
    } else {
        row[64] = __float2bfloat16(-1e30f);  // never wins (A k64 = 1)
    }
    __nv_bfloat16 sw[B_PITCH / 2];
#pragma unroll
    for (int i = 0; i < B_PITCH / 2; ++i) sw[i] = __float2bfloat16(0.f);
#pragma unroll
    for (int c = 0; c < 4; ++c)
#pragma unroll
        for (int kc = 0; kc < KC_N; ++kc)
#pragma unroll
            for (int hh = 0; hh < 2; ++hh) {
                int k = kc * 16 + hh * 8 + c * 2;
                sw[c * 24 + kc * 4 + hh * 2 + 0] = row[k];
                sw[c * 24 + kc * 4 + hh * 2 + 1] = row[k + 1];
            }
    uint4* dst = (uint4*)(g_B + (size_t)n * (B_PITCH / 2));
    const uint4* src = (const uint4*)sw;
#pragma unroll
    for (int i = 0; i < B_PITCH / 16; ++i) dst[i] = src[i];
}

// ---------------------------------------------------------------------------
__device__ __forceinline__ void mma16816(float* d, const uint32_t* a,
                                         const uint32_t* b) {
    asm volatile(
        "mma.sync.aligned.m16n8k16.row.col.f32.bf16.bf16.f32 "
        "{%0,%1,%2,%3}, {%4,%5,%6,%7}, {%8,%9}, {%0,%1,%2,%3};"
        : "+f"(d[0]), "+f"(d[1]), "+f"(d[2]), "+f"(d[3])
        : "r"(a[0]), "r"(a[1]), "r"(a[2]), "r"(a[3]), "r"(b[0]), "r"(b[1]));
}

// Group update: m = max of 4 candidates; b2' tracks 2nd-best GROUP max;
// rec records the group that last strictly improved b1.
__device__ __forceinline__ void upd4(float v0, float v1, float v2, float v3,
                                     int gid, float& b1, float& b2, int& rec) {
    float m = fmaxf(fmaxf(v0, v1), fmaxf(v2, v3));
    b2 = fmaxf(b2, fminf(b1, m));
    if (m > b1) rec = gid;
    b1 = fmaxf(b1, m);
}

__device__ __forceinline__ void load_bfrag(uint32_t bf[KC_N][2], const char* base) {
    uint4 w0 = *(const uint4*)(base);
    uint4 w1 = *(const uint4*)(base + 16);
    uint2 w2 = *(const uint2*)(base + 32);
    bf[0][0] = w0.x; bf[0][1] = w0.y; bf[1][0] = w0.z; bf[1][1] = w0.w;
    bf[2][0] = w1.x; bf[2][1] = w1.y; bf[3][0] = w1.z; bf[3][1] = w1.w;
    bf[4][0] = w2.x; bf[4][1] = w2.y;
}

// Exact R1-proven fp32 scoring (init -0.5*ysq, ascending fmaf chain)
__device__ __forceinline__ float score_one(const float* xs, const float4* yv,
                                           float ysq) {
    float4 y0 = yv[0], y1 = yv[1], y2 = yv[2], y3 = yv[3];
    float acc = -0.5f * ysq;
    acc = fmaf(xs[0], y0.x, acc);  acc = fmaf(xs[1], y0.y, acc);
    acc = fmaf(xs[2], y0.z, acc);  acc = fmaf(xs[3], y0.w, acc);
    acc = fmaf(xs[4], y1.x, acc);  acc = fmaf(xs[5], y1.y, acc);
    acc = fmaf(xs[6], y1.z, acc);  acc = fmaf(xs[7], y1.w, acc);
    acc = fmaf(xs[8], y2.x, acc);  acc = fmaf(xs[9], y2.y, acc);
    acc = fmaf(xs[10], y2.z, acc); acc = fmaf(xs[11], y2.w, acc);
    acc = fmaf(xs[12], y3.x, acc); acc = fmaf(xs[13], y3.y, acc);
    acc = fmaf(xs[14], y3.z, acc); acc = fmaf(xs[15], y3.w, acc);
    return acc;
}

// ---------------------------------------------------------------------------
// Main kernel: in-kernel A split; 256-vert B tiles (16 phases instead of 32);
// lean group-max epilogue; exact in-group resolve; fused rescue tail.
// ---------------------------------------------------------------------------
__global__ void __launch_bounds__(256, 2)
nn_mma_kernel(const float* __restrict__ x,
              const float* __restrict__ verts,
              const float* __restrict__ colors,
              float* __restrict__ out) {
    extern __shared__ char smem[];
    char* sA = smem + SMEM_A_OFF;
    char* sB = smem + SMEM_B_OFF;
    __shared__ int s_cnt;
    __shared__ int s_list[CTA_M];

    const int tid = threadIdx.x;
    const int w = tid >> 5;
    const int lane = tid & 31;
    const int g = lane >> 2;
    const int c = lane & 3;
    const int m0 = blockIdx.x * CTA_M;

    if (tid == 0) s_cnt = 0;

    // Build A stripe in smem: thread tid owns row tid (global row m0+tid).
    {
        const float4* xr = (const float4*)(x + (size_t)(m0 + tid) * DIMS);
        float xs[DIMS];
#pragma unroll
        for (int i = 0; i < 4; ++i) {
            float4 v = xr[i];
            xs[4 * i] = v.x; xs[4 * i + 1] = v.y;
            xs[4 * i + 2] = v.z; xs[4 * i + 3] = v.w;
        }
        __nv_bfloat16 row[KDIM];
#pragma unroll
        for (int k = 0; k < KDIM; ++k) row[k] = __float2bfloat16(0.f);
#pragma unroll
        for (int d = 0; d < DIMS; ++d) {
            __nv_bfloat16 a, b;
            split2(xs[d], a, b);
            row[0 + d] = a; row[16 + d] = a; row[32 + d] = b; row[48 + d] = b;
        }
        row[64] = __float2bfloat16(1.f);
        row[65] = __float2bfloat16(1.f);
        row[66] = __float2bfloat16(1.f);
        const uint4* src = (const uint4*)row;
        uint4* dst = (uint4*)(sA + tid * A_PITCH);
#pragma unroll
        for (int i = 0; i < 10; ++i) dst[i] = src[i];
    }
    __syncthreads();

    // A fragments: 2 stripes x 5 k-chunks x 4 regs (live all kernel)
    uint32_t af[2][KC_N][4];
#pragma unroll
    for (int s = 0; s < 2; ++s) {
        int r0 = w * 32 + s * 16 + g;
#pragma unroll
        for (int kc = 0; kc < KC_N; ++kc) {
            const char* base = sA + r0 * A_PITCH + kc * 32 + c * 4;
            af[s][kc][0] = *(const uint32_t*)(base);
            af[s][kc][1] = *(const uint32_t*)(base + 8 * A_PITCH);
            af[s][kc][2] = *(const uint32_t*)(base + 16);
            af[s][kc][3] = *(const uint32_t*)(base + 8 * A_PITCH + 16);
        }
    }

    float b1[4] = {-CUDART_INF_F, -CUDART_INF_F, -CUDART_INF_F, -CUDART_INF_F};
    float b2[4] = {-CUDART_INF_F, -CUDART_INF_F, -CUDART_INF_F, -CUDART_INF_F};
    int rec[4] = {0, 0, 0, 0};

    for (int t = 0; t < N_TILES; ++t) {
        __syncthreads();
        {
            const uint4* src = (const uint4*)(g_B + (size_t)t * TILE_N * (B_PITCH / 2));
            uint4* dst = (uint4*)sB;
            for (int i = tid; i < TILE_N * (B_PITCH / 16); i += 256) dst[i] = src[i];
        }
        __syncthreads();

#pragma unroll 1
        for (int nb2 = 0; nb2 < NB2_N; ++nb2) {
            uint32_t bfA[KC_N][2], bfB[KC_N][2];
            load_bfrag(bfA, sB + (nb2 * 16 + g) * B_PITCH + c * 48);
            load_bfrag(bfB, sB + (nb2 * 16 + 8 + g) * B_PITCH + c * 48);

            float a0A[4] = {0.f, 0.f, 0.f, 0.f};
            float a1A[4] = {0.f, 0.f, 0.f, 0.f};
            float a0B[4] = {0.f, 0.f, 0.f, 0.f};
            float a1B[4] = {0.f, 0.f, 0.f, 0.f};
#pragma unroll
            for (int kc = 0; kc < KC_N; ++kc) {
                mma16816(a0A, af[0][kc], bfA[kc]);
                mma16816(a1A, af[1][kc], bfA[kc]);
                mma16816(a0B, af[0][kc], bfB[kc]);
                mma16816(a1B, af[1][kc], bfB[kc]);
            }
            // group id: (t, nb2, c) packed (t<16, nb2<16, c<4)
            const int gid = (((t << 4) | nb2) << 2) | c;
            upd4(a0A[0], a0A[1], a0B[0], a0B[1], gid, b1[0], b2[0], rec[0]);
            upd4(a0A[2], a0A[3], a0B[2], a0B[3], gid, b1[1], b2[1], rec[1]);
            upd4(a1A[0], a1A[1], a1B[0], a1B[1], gid, b1[2], b2[2], rec[2]);
            upd4(a1A[2], a1A[3], a1B[2], a1B[3], gid, b1[3], b2[3], rec[3]);
        }
    }

    // Quad reduce (lanes 4g..4g+3 cover same rows, disjoint column groups).
#pragma unroll
    for (int off = 1; off <= 2; off <<= 1) {
#pragma unroll
        for (int r = 0; r < 4; ++r) {
            float ob1 = __shfl_xor_sync(0xFFFFFFFFu, b1[r], off);
            float ob2 = __shfl_xor_sync(0xFFFFFFFFu, b2[r], off);
            int orec = __shfl_xor_sync(0xFFFFFFFFu, rec[r], off);
            b2[r] = fmaxf(fmaxf(b2[r], ob2), fminf(b1[r], ob1));
            if (ob1 > b1[r]) rec[r] = orec;
            b1[r] = fmaxf(b1[r], ob1);
        }
    }

    if (c == 0) {
        const int rows[4] = {m0 + w * 32 + g,      m0 + w * 32 + g + 8,
                             m0 + w * 32 + g + 16, m0 + w * 32 + g + 24};
#pragma unroll
        for (int r = 0; r < 4; ++r) {
            if (b1[r] - b2[r] < TAU) {
                int f = atomicAdd(&s_cnt, 1);
                s_list[f] = rows[r];
            } else {
                // Winner provably in recorded group: resolve exactly in fp32.
                float xs[DIMS];
                const float4* xr = (const float4*)(x + (size_t)rows[r] * DIMS);
#pragma unroll
                for (int i = 0; i < 4; ++i) {
                    float4 v = xr[i];
                    xs[4 * i] = v.x; xs[4 * i + 1] = v.y;
                    xs[4 * i + 2] = v.z; xs[4 * i + 3] = v.w;
                }
                const int rv = rec[r];
                const int cw = rv & 3;
                const int tn = rv >> 2;
                const int base = (tn >> 4) * TILE_N + (tn & 15) * 16 + cw * 2;
                const int cols[4] = {base, base + 1, base + 8, base + 9};
                float bestv = -CUDART_INF_F;
                int bi = 0;
#pragma unroll
                for (int j = 0; j < 4; ++j) {
                    const int v = cols[j];
                    if (v < N_VERTS) {
                        float s = score_one(xs, (const float4*)(verts + (size_t)v * DIMS),
                                            g_ysq[v]);
                        if (s > bestv) { bestv = s; bi = v; }
                    }
                }
                const float* cc = colors + (size_t)3 * bi;
                float* o = out + (size_t)3 * rows[r];
                o[0] = cc[0]; o[1] = cc[1]; o[2] = cc[2];
            }
        }
    }
    __syncthreads();

    // ---- Fused rescue tail: warp-per-flagged-row exact fp32 argmax ----
    const int cntL = s_cnt;
    for (int f = w; f < cntL; f += 8) {
        const int row = s_list[f];
        float xs[DIMS];
        const float4* xr = (const float4*)(x + (size_t)row * DIMS);
#pragma unroll
        for (int i = 0; i < 4; ++i) {
            float4 v = xr[i];
            xs[4 * i] = v.x; xs[4 * i + 1] = v.y;
            xs[4 * i + 2] = v.z; xs[4 * i + 3] = v.w;
        }

        float best = -CUDART_INF_F;
        int bi = N_VERTS;
        for (int base = 0; base < 3968; base += 128) {
            const int v0 = base + lane * 4;
            const float4* yv = (const float4*)(verts + (size_t)v0 * DIMS);
            float s0 = score_one(xs, yv + 0,  g_ysq[v0 + 0]);
            float s1 = score_one(xs, yv + 4,  g_ysq[v0 + 1]);
            float s2 = score_one(xs, yv + 8,  g_ysq[v0 + 2]);
            float s3 = score_one(xs, yv + 12, g_ysq[v0 + 3]);
            if (s0 > best) { best = s0; bi = v0; }
            if (s1 > best) { best = s1; bi = v0 + 1; }
            if (s2 > best) { best = s2; bi = v0 + 2; }
            if (s3 > best) { best = s3; bi = v0 + 3; }
        }
        {   // tail verts 3968..3999
            const int v0 = 3968 + lane;
            const float4* yv = (const float4*)(verts + (size_t)v0 * DIMS);
            float s0 = score_one(xs, yv, g_ysq[v0]);
            if (s0 > best) { best = s0; bi = v0; }
        }
#pragma unroll
        for (int off = 16; off > 0; off >>= 1) {
            float os = __shfl_down_sync(0xFFFFFFFF, best, off);
            int oi = __shfl_down_sync(0xFFFFFFFF, bi, off);
            if (os > best || (os == best && oi < bi)) { best = os; bi = oi; }
        }
        if (lane == 0) {
            const float* cc = colors + (size_t)3 * bi;
            float* o = out + (size_t)3 * row;
            o[0] = cc[0]; o[1] = cc[1]; o[2] = cc[2];
        }
    }
}

extern "C" void kernel_launch(void* const* d_in, const int* in_sizes, int n_in,
                              void* d_out, int out_size) {
    const float* cse    = (const float*)d_in[0];  // (M,16) f32
    const float* colors = (const float*)d_in[1];  // (N,3)  f32
    const float* vemb   = (const float*)d_in[2];  // (N,16) f32
    float* out = (float*)d_out;                   // (M,3)  f32

    cudaFuncSetAttribute(nn_mma_kernel,
                         cudaFuncAttributeMaxDynamicSharedMemorySize, SMEM_TOTAL);

    prep_b<<<(N_PAD + 255) / 256, 256>>>(vemb);
    nn_mma_kernel<<<GRID_M, 256, SMEM_TOTAL>>>(cse, vemb, colors, out);
}